// round 12
// baseline (speedup 1.0000x reference)
#include <cuda_runtime.h>
#include <cstdint>

// QuantizedLinear: y[b,o] = scale[o] * sum_k x[b,k]*W[o,k] + bias[o]
//   x: f32 [16,4096], W: int32 [11008,4096] (int8-range), scale/bias f32,
//   out f32 [16,11008].
//
// R11: occupancy push. R10 sat at 3 CTAs/SM (168 regs, issue 32%).
//   - Each k-iter split into two phases (k0/k1 via smem half A, k2/k3 via B)
//     so only 8 weight-dup regs are live at once (reused between phases) and
//     the redundant wi[] copy is gone. Live set ~110 regs.
//   - __launch_bounds__(128, 4): 4 CTAs/SM = 16 warps, smem 4x32KB = 132KB.
//   - Weight prefetch issued mid-iter (right after wn fully consumed), giving
//     ~1 full iter (~740 cyc @4 warps/SMSP) of coverage vs 577-cyc DRAM.
//   - x staged in smem batch-pair-packed + lane-swizzled (16B lane stride ->
//     conflict-free LDS.128); weights stream once via __ldcs.

#define IN_F     4096
#define OUT_F    11008
#define BATCH    16
#define NPAIR    8                     // batch pairs
#define CH       4                     // output channels per warp
#define WARPS    4
#define THREADS  (WARPS * 32)          // 128
#define KV_ROW   (IN_F / 4)            // 1024 int4/float4 per row
#define CHUNK_KV 128                   // k-quads per chunk = 512 k
#define NCHUNK   (KV_ROW / CHUNK_KV)   // 8
#define ITERS    (CHUNK_KV / 32)       // 4 iters per chunk
#define GITERS   (NCHUNK * ITERS)      // 32 total k-iters

__device__ __forceinline__ unsigned long long dup_f32(float a) {
    unsigned long long r;
    asm("mov.b64 %0, {%1, %1};" : "=l"(r) : "f"(a));
    return r;
}

__device__ __forceinline__ void fma2(unsigned long long& acc,
                                     unsigned long long a,
                                     unsigned long long b) {
    asm("fma.rn.f32x2 %0, %1, %2, %0;" : "+l"(acc) : "l"(a), "l"(b));
}

__global__ void __launch_bounds__(THREADS, 4)
qlin_kernel(const float4* __restrict__ X,     // x as [16][1024] float4
            const int4*   __restrict__ Wv,    // W as [11008][1024] int4
            const float*  __restrict__ scale,
            const float*  __restrict__ bias,
            float*        __restrict__ out)
{
    // Swizzled pair-packed x chunk, 32 KB:
    // float4 xs[it(4)][p(8)][ab(2)][lane(32)]
    //   A[lane] = {x[2p][k0], x[2p+1][k0], x[2p][k1], x[2p+1][k1]}
    //   B[lane] = {x[2p][k2], x[2p+1][k2], x[2p][k3], x[2p+1][k3]}
    // with k0..k3 = 4*(chunk*128 + it*32 + lane) ..+3
    __shared__ float4 xs[ITERS * NPAIR * 2 * 32];

    const int tid  = threadIdx.x;
    const int lane = tid & 31;
    const int warp = tid >> 5;
    const int o0   = (blockIdx.x * WARPS + warp) * CH;

    unsigned long long acc[CH][NPAIR];
#pragma unroll
    for (int c = 0; c < CH; ++c)
#pragma unroll
        for (int p = 0; p < NPAIR; ++p) acc[c][p] = 0ull;

    const long long wrow = (long long)o0 * KV_ROW;

    // Prefetch weights for global iter 0.
    int4 wn[CH];
#pragma unroll
    for (int c = 0; c < CH; ++c)
        wn[c] = __ldcs(&Wv[wrow + c * KV_ROW + lane]);

#pragma unroll 1
    for (int chunk = 0; chunk < NCHUNK; ++chunk) {
        __syncthreads();   // prior chunk's reads complete before overwrite

        // Stage: 1024 (p,kvl) items, 8 per thread (it=tid>>5, ln=tid&31).
        {
            const int it = tid >> 5;
            const int ln = tid & 31;
#pragma unroll
            for (int p = 0; p < NPAIR; ++p) {
                const float4 r0 = X[(2 * p)     * KV_ROW + chunk * CHUNK_KV + tid];
                const float4 r1 = X[(2 * p + 1) * KV_ROW + chunk * CHUNK_KV + tid];
                float4 A, B;
                A.x = r0.x; A.y = r1.x; A.z = r0.y; A.w = r1.y;
                B.x = r0.z; B.y = r1.z; B.z = r0.w; B.w = r1.w;
                xs[((it * NPAIR + p) * 2 + 0) * 32 + ln] = A;
                xs[((it * NPAIR + p) * 2 + 1) * 32 + ln] = B;
            }
        }
        __syncthreads();

#pragma unroll
        for (int it = 0; it < ITERS; ++it) {
            const float4* xbase = &xs[(it * NPAIR) * 2 * 32 + lane];

            // ---- Phase A: k0,k1 (wn.x, wn.y) ----
            unsigned long long wa[CH], wb[CH];
#pragma unroll
            for (int c = 0; c < CH; ++c) {
                wa[c] = dup_f32((float)wn[c].x);
                wb[c] = dup_f32((float)wn[c].y);
            }
#pragma unroll
            for (int p = 0; p < NPAIR; ++p) {
                const ulonglong2 A = *reinterpret_cast<const ulonglong2*>(
                    xbase + (p * 2 + 0) * 32);
#pragma unroll
                for (int c = 0; c < CH; ++c) {
                    fma2(acc[c][p], wa[c], A.x);   // k0, batches {2p,2p+1}
                    fma2(acc[c][p], wb[c], A.y);   // k1
                }
            }

            // ---- Phase B setup: consume wn.z/.w, then free wn via prefetch.
#pragma unroll
            for (int c = 0; c < CH; ++c) {
                wa[c] = dup_f32((float)wn[c].z);
                wb[c] = dup_f32((float)wn[c].w);
            }
            const int gn = chunk * ITERS + it + 1;
            if (gn < GITERS) {
#pragma unroll
                for (int c = 0; c < CH; ++c)
                    wn[c] = __ldcs(&Wv[wrow + c * KV_ROW + gn * 32 + lane]);
            }

            // ---- Phase B: k2,k3 ----
#pragma unroll
            for (int p = 0; p < NPAIR; ++p) {
                const ulonglong2 B = *reinterpret_cast<const ulonglong2*>(
                    xbase + (p * 2 + 1) * 32);
#pragma unroll
                for (int c = 0; c < CH; ++c) {
                    fma2(acc[c][p], wa[c], B.x);   // k2
                    fma2(acc[c][p], wb[c], B.y);   // k3
                }
            }
        }
    }

    // Epilogue: each acc half is one output's lane-partial. Reduce, scale+bias.
#pragma unroll
    for (int c = 0; c < CH; ++c) {
        const int   o  = o0 + c;
        const float sc = scale[o];
        const float bi = bias[o];
#pragma unroll
        for (int p = 0; p < NPAIR; ++p) {
            float lo, hi;
            asm("mov.b64 {%0, %1}, %2;" : "=f"(lo), "=f"(hi) : "l"(acc[c][p]));
#pragma unroll
            for (int off = 16; off > 0; off >>= 1) {
                lo += __shfl_xor_sync(0xffffffffu, lo, off);
                hi += __shfl_xor_sync(0xffffffffu, hi, off);
            }
            if (lane == 0) {
                out[(2 * p)     * OUT_F + o] = lo * sc + bi;
                out[(2 * p + 1) * OUT_F + o] = hi * sc + bi;
            }
        }
    }
}

extern "C" void kernel_launch(void* const* d_in, const int* in_sizes, int n_in,
                              void* d_out, int out_size) {
    // metadata order: x (f32), weight_int8 (int32), weight_scale (f32), bias (f32)
    const float4* X     = (const float4*)d_in[0];
    const int4*   Wv    = (const int4*)d_in[1];
    const float*  scale = (const float*)d_in[2];
    const float*  bias  = (const float*)d_in[3];
    float*        out   = (float*)d_out;
    (void)in_sizes; (void)n_in; (void)out_size;

    const int blocks = OUT_F / (WARPS * CH);   // 688
    qlin_kernel<<<blocks, THREADS>>>(X, Wv, scale, bias, out);
}

// round 13
// speedup vs baseline: 1.1274x; 1.1274x over previous
#include <cuda_runtime.h>
#include <cstdint>

// QuantizedLinear: y[b,o] = scale[o] * sum_k x[b,k]*W[o,k] + bias[o]
//   x: f32 [16,4096], W: int32 [11008,4096] (int8-range), scale/bias f32,
//   out f32 [16,11008].
//
// R12: decouple weight-DRAM latency from registers/occupancy.
//   - Weights stream via cp.async.bulk (UBLKCP) into double-buffered smem
//     (2 x 16KB per CTA), mbarrier full/empty pipeline. In-flight DRAM bytes
//     per SM = 3 CTAs x 16KB = 48KB >> ~17KB needed to saturate HBM, with
//     ZERO register cost (R10/R11 register-prefetch capped at ~8KB/SM).
//   - Tile: warp = 8 channels x 8 batches (batch split across warp pairs);
//     acc stays 64 regs, x-LDS halves -> smem read (8 w + 8 x LDS.128 =
//     64 cyc) balances fma (128 FFMA2 = 64 cyc) per warp-iter.
//   - x keeps R11's swizzled batch-pair smem staging (conflict-free LDS.128,
//     no packing MOVs on hot path).
//   - 688 CTAs x 128 thr; smem 64KB+ -> 3 CTAs/SM (launch_bounds(128,3)).

#define IN_F     4096
#define OUT_F    11008
#define BATCH    16
#define CH       8                     // channels per warp
#define NP       4                     // batch-pairs per warp (8 batches)
#define WARPS    4
#define THREADS  128
#define KV_ROW   (IN_F / 4)            // 1024 quads per row
#define CHUNK_KV 128                   // x-chunk: 512 k
#define NCHUNK   8
#define SUB_KV   64                    // weight subchunk: 256 k
#define NSUB     16
#define ROWS_CTA 16                    // channels per CTA
#define WBUF_B   (ROWS_CTA * SUB_KV * 16)   // 16384 B per weight buffer
#define XS_B     (4 * 8 * 2 * 32 * 16)      // 32768 B swizzled x chunk
#define SMEM_B   (XS_B + 2 * WBUF_B + 64)   // + mbarriers

__device__ __forceinline__ uint32_t smem_u32(const void* p) {
    uint32_t a;
    asm("{ .reg .u64 t; cvta.to.shared.u64 t, %1; cvt.u32.u64 %0, t; }"
        : "=r"(a) : "l"(p));
    return a;
}

__device__ __forceinline__ void mbar_init(uint32_t a, uint32_t cnt) {
    asm volatile("mbarrier.init.shared.b64 [%0], %1;" :: "r"(a), "r"(cnt) : "memory");
}
__device__ __forceinline__ void mbar_expect_tx(uint32_t a, uint32_t bytes) {
    asm volatile("mbarrier.arrive.expect_tx.shared.b64 _, [%0], %1;"
                 :: "r"(a), "r"(bytes) : "memory");
}
__device__ __forceinline__ void mbar_arrive(uint32_t a) {
    asm volatile("mbarrier.arrive.shared.b64 _, [%0];" :: "r"(a) : "memory");
}
__device__ __forceinline__ void mbar_wait(uint32_t a, uint32_t ph) {
    uint32_t done;
    asm volatile(
        "{\n\t.reg .pred p;\n\t"
        "mbarrier.try_wait.parity.acquire.cta.shared::cta.b64 p, [%1], %2;\n\t"
        "selp.b32 %0, 1, 0, p;\n\t}"
        : "=r"(done) : "r"(a), "r"(ph) : "memory");
    if (!done) {
        asm volatile(
            "{\n\t.reg .pred P1;\n\t"
            "W_%=:\n\t"
            "mbarrier.try_wait.parity.acquire.cta.shared::cta.b64 P1, [%0], %1, 0x989680;\n\t"
            "@P1 bra.uni D_%=;\n\t"
            "bra.uni W_%=;\n\t"
            "D_%=:\n\t}"
            :: "r"(a), "r"(ph) : "memory");
    }
}
__device__ __forceinline__ void bulk_cp(uint32_t dst, const void* src,
                                        uint32_t bytes, uint32_t mbar) {
    asm volatile(
        "cp.async.bulk.shared::cluster.global.mbarrier::complete_tx::bytes "
        "[%0], [%1], %2, [%3];"
        :: "r"(dst), "l"(src), "r"(bytes), "r"(mbar) : "memory");
}

__device__ __forceinline__ unsigned long long dup_f32(float a) {
    unsigned long long r;
    asm("mov.b64 %0, {%1, %1};" : "=l"(r) : "f"(a));
    return r;
}
__device__ __forceinline__ void fma2(unsigned long long& acc,
                                     unsigned long long a,
                                     unsigned long long b) {
    asm("fma.rn.f32x2 %0, %1, %2, %0;" : "+l"(acc) : "l"(a), "l"(b));
}

extern __shared__ char smem[];

__global__ void __launch_bounds__(THREADS, 3)
qlin_kernel(const float4* __restrict__ X,     // x as [16][1024] float4
            const int*    __restrict__ W,     // W as [11008][4096] int32
            const float*  __restrict__ scale,
            const float*  __restrict__ bias,
            float*        __restrict__ out)
{
    // smem: [0,32KB) xs swizzled x chunk; [32KB,+16KB)x2 weight bufs; mbars.
    float4* xs = reinterpret_cast<float4*>(smem);
    char*   wb = smem + XS_B;
    const uint32_t sbase = smem_u32(smem);
    const uint32_t mb    = sbase + XS_B + 2 * WBUF_B;   // 4 x 8B mbarriers
    // mb+0: full0, mb+8: full1, mb+16: empty0, mb+24: empty1

    const int tid  = threadIdx.x;
    const int lane = tid & 31;
    const int warp = tid >> 5;
    const int o_base = blockIdx.x * ROWS_CTA;
    const int rgrp   = (warp >> 1) * CH;   // channel row base within CTA
    const int po     = (warp & 1) * NP;    // batch-pair offset

    if (tid == 0) {
        mbar_init(mb + 0,  1);        // full0 (tx-based)
        mbar_init(mb + 8,  1);        // full1
        mbar_init(mb + 16, THREADS);  // empty0
        mbar_init(mb + 24, THREADS);  // empty1
    }
    __syncthreads();

    // Prologue: issue weight subchunks 0 and 1.
    if (tid == 0) {
#pragma unroll 1
        for (int s = 0; s < 2; ++s) {
            const uint32_t fullb = mb + (s & 1) * 8;
            mbar_expect_tx(fullb, WBUF_B);
            const uint32_t dst = sbase + XS_B + (s & 1) * WBUF_B;
            const char* wsrc = reinterpret_cast<const char*>(W) + (size_t)s * 1024;
#pragma unroll
            for (int r = 0; r < ROWS_CTA; ++r)
                bulk_cp(dst + r * 1024,
                        wsrc + (size_t)(o_base + r) * (IN_F * 4),
                        1024, fullb);
        }
    }

    unsigned long long acc[CH][NP];
#pragma unroll
    for (int c = 0; c < CH; ++c)
#pragma unroll
        for (int p = 0; p < NP; ++p) acc[c][p] = 0ull;

#pragma unroll 1
    for (int chunk = 0; chunk < NCHUNK; ++chunk) {
        __syncthreads();   // prior chunk's x reads complete before overwrite
        // Stage x chunk swizzled: xs[it(4)][p(8)][ab(2)][lane(32)] float4
        {
            const int it = tid >> 5;
            const int ln = tid & 31;
#pragma unroll
            for (int p = 0; p < 8; ++p) {
                const float4 r0 = X[(2 * p)     * KV_ROW + chunk * CHUNK_KV + tid];
                const float4 r1 = X[(2 * p + 1) * KV_ROW + chunk * CHUNK_KV + tid];
                float4 A, B;
                A.x = r0.x; A.y = r1.x; A.z = r0.y; A.w = r1.y;
                B.x = r0.z; B.y = r1.z; B.z = r0.w; B.w = r1.w;
                xs[((it * 8 + p) * 2 + 0) * 32 + ln] = A;
                xs[((it * 8 + p) * 2 + 1) * 32 + ln] = B;
            }
        }
        __syncthreads();

#pragma unroll
        for (int half = 0; half < 2; ++half) {
            const int s  = chunk * 2 + half;       // weight subchunk 0..15
            const int bi = s & 1;
            const uint32_t ph = (uint32_t)((s >> 1) & 1);
            const uint32_t fullb = mb + bi * 8;
            const uint32_t empb  = mb + 16 + bi * 8;

            mbar_wait(fullb, ph);
            const char* wbuf = wb + bi * WBUF_B;

#pragma unroll
            for (int i = 0; i < 2; ++i) {
                const int kvl = i * 32 + lane;         // 0..63 within sub
                const int it  = half * 2 + i;          // x-chunk iter 0..3

                int4 wq[CH];
#pragma unroll
                for (int c = 0; c < CH; ++c)
                    wq[c] = *reinterpret_cast<const int4*>(
                        wbuf + (rgrp + c) * (SUB_KV * 16) + kvl * 16);

                const float4* xbase = &xs[(it * 8 + po) * 2 * 32 + lane];

                // Phase A: k0,k1
                unsigned long long wa[CH], wbv[CH];
#pragma unroll
                for (int c = 0; c < CH; ++c) {
                    wa[c]  = dup_f32((float)wq[c].x);
                    wbv[c] = dup_f32((float)wq[c].y);
                }
#pragma unroll
                for (int p = 0; p < NP; ++p) {
                    const ulonglong2 A = *reinterpret_cast<const ulonglong2*>(
                        xbase + (p * 2 + 0) * 32);
#pragma unroll
                    for (int c = 0; c < CH; ++c) {
                        fma2(acc[c][p], wa[c],  A.x);   // k0
                        fma2(acc[c][p], wbv[c], A.y);   // k1
                    }
                }
                // Phase B: k2,k3
#pragma unroll
                for (int c = 0; c < CH; ++c) {
                    wa[c]  = dup_f32((float)wq[c].z);
                    wbv[c] = dup_f32((float)wq[c].w);
                }
#pragma unroll
                for (int p = 0; p < NP; ++p) {
                    const ulonglong2 B = *reinterpret_cast<const ulonglong2*>(
                        xbase + (p * 2 + 1) * 32);
#pragma unroll
                    for (int c = 0; c < CH; ++c) {
                        fma2(acc[c][p], wa[c],  B.x);   // k2
                        fma2(acc[c][p], wbv[c], B.y);   // k3
                    }
                }
            }

            mbar_arrive(empb);   // this thread done reading wbuf[bi]
            if (tid == 0 && s + 2 < NSUB) {
                mbar_wait(empb, ph);                 // all 128 arrived
                mbar_expect_tx(fullb, WBUF_B);
                const uint32_t dst = sbase + XS_B + bi * WBUF_B;
                const char* wsrc = reinterpret_cast<const char*>(W)
                                 + (size_t)(s + 2) * 1024;
#pragma unroll
                for (int r = 0; r < ROWS_CTA; ++r)
                    bulk_cp(dst + r * 1024,
                            wsrc + (size_t)(o_base + r) * (IN_F * 4),
                            1024, fullb);
            }
        }
    }

    // Epilogue: warp-reduce lane partials, scale + bias, store.
#pragma unroll
    for (int c = 0; c < CH; ++c) {
        const int   o  = o_base + rgrp + c;
        const float sc = scale[o];
        const float bi = bias[o];
#pragma unroll
        for (int p = 0; p < NP; ++p) {
            float lo, hi;
            asm("mov.b64 {%0, %1}, %2;" : "=f"(lo), "=f"(hi) : "l"(acc[c][p]));
#pragma unroll
            for (int off = 16; off > 0; off >>= 1) {
                lo += __shfl_xor_sync(0xffffffffu, lo, off);
                hi += __shfl_xor_sync(0xffffffffu, hi, off);
            }
            if (lane == 0) {
                const int b0 = 2 * (po + p);
                out[b0       * OUT_F + o] = lo * sc + bi;
                out[(b0 + 1) * OUT_F + o] = hi * sc + bi;
            }
        }
    }
}

extern "C" void kernel_launch(void* const* d_in, const int* in_sizes, int n_in,
                              void* d_out, int out_size) {
    // metadata order: x (f32), weight_int8 (int32), weight_scale (f32), bias (f32)
    const float4* X     = (const float4*)d_in[0];
    const int*    W     = (const int*)d_in[1];
    const float*  scale = (const float*)d_in[2];
    const float*  bias  = (const float*)d_in[3];
    float*        out   = (float*)d_out;
    (void)in_sizes; (void)n_in; (void)out_size;

    cudaFuncSetAttribute(qlin_kernel,
                         cudaFuncAttributeMaxDynamicSharedMemorySize, SMEM_B);
    const int blocks = OUT_F / ROWS_CTA;   // 688
    qlin_kernel<<<blocks, THREADS, SMEM_B>>>(X, W, scale, bias, out);
}